// round 15
// baseline (speedup 1.0000x reference)
#include <cuda_runtime.h>

// Sobel |gx|+|gy|+eps over (32,1,1024,1024) f32, SAME zero padding.
// R4 structure: per-thread 4-wide x 16-tall strip, 3-row rolling window,
// raw rows prefetched 2 iterations ahead, shuffle halo, .cs stores.
// Single change vs R4: __launch_bounds__(256, 6) -> 42-reg cap,
// 6 blocks/SM = 48 warps (75% occ) for more in-flight DRAM demand.

#define IMG_W 1024
#define IMG_H 1024
#define C4    (IMG_W / 4)   // 256 float4 columns per row
#define RPT   16            // output rows per thread
#define RB    (IMG_H / RPT) // 64 row-blocks per image

struct RawRow {
    float4 c;
    float  e;   // lane 0: left halo; lane 31: right halo; others unused
};

__device__ __forceinline__ RawRow load_raw(const float* __restrict__ base,
                                           bool in, int c4, int lane) {
    RawRow o;
    o.c = make_float4(0.f, 0.f, 0.f, 0.f);
    o.e = 0.f;
    if (in) {
        o.c = *reinterpret_cast<const float4*>(base);
        if (lane == 0) {
            if (c4 > 0) o.e = __ldg(base - 1);
        } else if (lane == 31) {
            if (c4 < C4 - 1) o.e = __ldg(base + 4);
        }
    }
    return o;
}

__device__ __forceinline__ void expand(const RawRow& rr, int lane, float v[6]) {
    float left  = __shfl_up_sync(0xFFFFFFFFu, rr.c.w, 1);
    float right = __shfl_down_sync(0xFFFFFFFFu, rr.c.x, 1);
    if (lane == 0)  left  = rr.e;
    if (lane == 31) right = rr.e;
    v[0] = left;
    v[1] = rr.c.x; v[2] = rr.c.y; v[3] = rr.c.z; v[4] = rr.c.w;
    v[5] = right;
}

__global__ void __launch_bounds__(256, 6)
sobel_grad_kernel(const float* __restrict__ x, float* __restrict__ out) {
    int idx  = blockIdx.x * blockDim.x + threadIdx.x;
    int lane = threadIdx.x & 31;
    int c4 = idx & (C4 - 1);          // float4 column  (0..255)
    int t  = idx >> 8;
    int rb = t & (RB - 1);            // row block      (0..63)
    int n  = t >> 6;                  // image index    (0..31)

    int row0 = rb * RPT;
    const float* ibase = x + (size_t)n * IMG_H * IMG_W + (size_t)c4 * 4;
    float*       obase = out + (size_t)n * IMG_H * IMG_W + (size_t)c4 * 4
                             + (size_t)row0 * IMG_W;

    float top[6], mid[6], bot[6];
    RawRow praw;

    // Prologue: rows row0-1 .. row0+1 expanded, row0+2 raw-prefetched.
    {
        const float* p = ibase + (size_t)(row0 - 1) * IMG_W;
        RawRow r0 = load_raw(p,             row0 - 1 >= 0,     c4, lane);
        RawRow r1 = load_raw(p + IMG_W,     true,              c4, lane);
        RawRow r2 = load_raw(p + 2 * IMG_W, true,              c4, lane);
        praw      = load_raw(p + 3 * IMG_W, row0 + 2 < IMG_H,  c4, lane);
        expand(r0, lane, top);
        expand(r1, lane, mid);
        expand(r2, lane, bot);
    }

    const float* pf = ibase + (size_t)(row0 + 3) * IMG_W;

    #pragma unroll
    for (int i = 0; i < RPT; i++) {
        // Register prefetch raw row row0+i+3 (consumed 2 iterations later).
        RawRow nraw;
        if (i < RPT - 2)
            nraw = load_raw(pf, row0 + i + 3 < IMG_H, c4, lane);
        pf += IMG_W;

        float o0, o1, o2, o3;
        {
            float gx, gy;
            gx = (top[2] - top[0]) + 2.0f * (mid[2] - mid[0]) + (bot[2] - bot[0]);
            gy = (bot[0] - top[0]) + 2.0f * (bot[1] - top[1]) + (bot[2] - top[2]);
            o0 = fabsf(gx) + fabsf(gy) + 1e-5f;
            gx = (top[3] - top[1]) + 2.0f * (mid[3] - mid[1]) + (bot[3] - bot[1]);
            gy = (bot[1] - top[1]) + 2.0f * (bot[2] - top[2]) + (bot[3] - top[3]);
            o1 = fabsf(gx) + fabsf(gy) + 1e-5f;
            gx = (top[4] - top[2]) + 2.0f * (mid[4] - mid[2]) + (bot[4] - bot[2]);
            gy = (bot[2] - top[2]) + 2.0f * (bot[3] - top[3]) + (bot[4] - top[4]);
            o2 = fabsf(gx) + fabsf(gy) + 1e-5f;
            gx = (top[5] - top[3]) + 2.0f * (mid[5] - mid[3]) + (bot[5] - bot[3]);
            gy = (bot[3] - top[3]) + 2.0f * (bot[4] - top[4]) + (bot[5] - top[5]);
            o3 = fabsf(gx) + fabsf(gy) + 1e-5f;
        }
        __stcs(reinterpret_cast<float4*>(obase), make_float4(o0, o1, o2, o3));
        obase += IMG_W;

        if (i < RPT - 1) {
            #pragma unroll
            for (int k = 0; k < 6; k++) { top[k] = mid[k]; mid[k] = bot[k]; }
            expand(praw, lane, bot);
            praw = nraw;
        }
    }
}

extern "C" void kernel_launch(void* const* d_in, const int* in_sizes, int n_in,
                              void* d_out, int out_size) {
    const float* x = (const float*)d_in[0];
    float* out = (float*)d_out;

    int total_threads = out_size / (4 * RPT);     // 524288
    int blocks = (total_threads + 255) / 256;     // 2048
    sobel_grad_kernel<<<blocks, 256>>>(x, out);
}

// round 16
// speedup vs baseline: 1.2231x; 1.2231x over previous
#include <cuda_runtime.h>

// Sobel |gx|+|gy|+eps over (32,1,1024,1024) f32, SAME zero padding.
// Flattened-row strips: 32768 independent rows split into 2220 blocks
// (= exactly 3 waves of 148 SMs x 5 blocks). Strips may cross image
// boundaries; vertical zero-padding applied per output row via FMA masks
// (mt/mb), folded into the stencil at no SEL cost. Pipeline = R4: 3-row
// rolling window, raw rows prefetched 2 iterations ahead, shuffle halo,
// .cs streaming stores. 256 thr/block cover the full 1024-wide row.

#define IMG_W 1024
#define G_ROWS 32768        // 32 images * 1024 rows, flattened
#define NBLK  2220          // 3 * 148 * 5 — exact 3 waves at 5 blocks/SM
#define B15   1688          // first B15 blocks do 15 rows, rest do 14
#define HMAX  15

struct RawRow {
    float4 c;
    float  e;   // lane 0: left halo; lane 31: right halo; others unused
};

__device__ __forceinline__ RawRow load_raw(const float* __restrict__ base,
                                           bool in, int c4, int lane) {
    RawRow o;
    o.c = make_float4(0.f, 0.f, 0.f, 0.f);
    o.e = 0.f;
    if (in) {
        o.c = *reinterpret_cast<const float4*>(base);
        if (lane == 0) {
            if (c4 > 0) o.e = __ldg(base - 1);
        } else if (lane == 31) {
            if (c4 < 255) o.e = __ldg(base + 4);
        }
    }
    return o;
}

__device__ __forceinline__ void expand(const RawRow& rr, int lane, float v[6]) {
    float left  = __shfl_up_sync(0xFFFFFFFFu, rr.c.w, 1);
    float right = __shfl_down_sync(0xFFFFFFFFu, rr.c.x, 1);
    if (lane == 0)  left  = rr.e;
    if (lane == 31) right = rr.e;
    v[0] = left;
    v[1] = rr.c.x; v[2] = rr.c.y; v[3] = rr.c.z; v[4] = rr.c.w;
    v[5] = right;
}

__global__ void __launch_bounds__(256, 5)
sobel_grad_kernel(const float* __restrict__ x, float* __restrict__ out) {
    int c4   = threadIdx.x;            // float4 column (0..255)
    int lane = c4 & 31;
    int b    = blockIdx.x;

    int row0 = 14 * b + min(b, B15);   // flattened start row
    int h    = (b < B15) ? 15 : 14;    // rows this block

    const float* ibase = x   + (size_t)c4 * 4;
    float*       obase = out + (size_t)c4 * 4 + (size_t)row0 * IMG_W;

    float top[6], mid[6], bot[6];
    RawRow praw;

    // Prologue: flattened rows row0-1 .. row0+1 expanded, row0+2 raw.
    {
        const float* p = ibase + (size_t)(row0 - 1) * IMG_W;
        RawRow r0 = load_raw(p,             row0 - 1 >= 0,       c4, lane);
        RawRow r1 = load_raw(p + IMG_W,     true,                c4, lane);
        RawRow r2 = load_raw(p + 2 * IMG_W, row0 + 1 < G_ROWS,   c4, lane);
        praw      = load_raw(p + 3 * IMG_W, row0 + 2 < G_ROWS,   c4, lane);
        expand(r0, lane, top);
        expand(r1, lane, mid);
        expand(r2, lane, bot);
    }

    const float* pf = ibase + (size_t)(row0 + 3) * IMG_W;

    #pragma unroll
    for (int i = 0; i < HMAX; i++) {
        if (i >= h) break;

        // Raw prefetch flattened row row0+i+3 (consumed 2 iters later).
        RawRow nraw;
        if (i < h - 2)
            nraw = load_raw(pf, row0 + i + 3 < G_ROWS, c4, lane);
        pf += IMG_W;

        // Vertical zero-pad masks at image boundaries (rows independent
        // across images; top row of an image sees 0 above, bottom sees 0
        // below). Folded into the stencil as FMA multipliers.
        int rmod = (row0 + i) & 1023;
        float mt = (rmod != 0)    ? 1.0f : 0.0f;
        float mb = (rmod != 1023) ? 1.0f : 0.0f;

        float o[4];
        #pragma unroll
        for (int j = 0; j < 4; j++) {
            float dt = top[j + 2] - top[j];
            float dm = mid[j + 2] - mid[j];
            float db = bot[j + 2] - bot[j];
            float gx = fmaf(mt, dt, fmaf(mb, db, 2.0f * dm));
            float st = top[j] + 2.0f * top[j + 1] + top[j + 2];
            float sb = bot[j] + 2.0f * bot[j + 1] + bot[j + 2];
            float gy = fmaf(mb, sb, -(mt * st));
            o[j] = fabsf(gx) + fabsf(gy) + 1e-5f;
        }
        __stcs(reinterpret_cast<float4*>(obase), make_float4(o[0], o[1], o[2], o[3]));
        obase += IMG_W;

        if (i < h - 1) {
            #pragma unroll
            for (int k = 0; k < 6; k++) { top[k] = mid[k]; mid[k] = bot[k]; }
            expand(praw, lane, bot);
            praw = nraw;
        }
    }
}

extern "C" void kernel_launch(void* const* d_in, const int* in_sizes, int n_in,
                              void* d_out, int out_size) {
    const float* x = (const float*)d_in[0];
    float* out = (float*)d_out;

    sobel_grad_kernel<<<NBLK, 256>>>(x, out);
}